// round 2
// baseline (speedup 1.0000x reference)
#include <cuda_runtime.h>
#include <cuda_bf16.h>
#include <math.h>

// Problem constants
#define BV   32000
#define TT   2048
#define HH   4
#define NN_  4096
#define DD   256
#define LL   6
#define KK   1024     // N/H
#define BB   2
#define EPS  1e-5f

// ---------------- scratch (device globals; no mallocs allowed) ----------------
__device__ float g_v[BB*TT*DD];             // 4 MB
__device__ float g_x[BB*HH*TT*KK];          // 64 MB   [B,H,T,K]
__device__ float g_q[BB*HH*TT*KK];          // 64 MB
__device__ float g_scores[BB*HH*TT*TT];     // 128 MB  [B,H,T,T]
__device__ float g_a[BB*HH*TT*DD];          // 16 MB
__device__ float g_y[BB*TT*NN_];            // 32 MB   [B,T,N]
__device__ float g_yE[BB*TT*DD];            // 4 MB
__device__ float g_cos[TT*KK];              // 8 MB
__device__ float g_sin[TT*KK];              // 8 MB

// ---------------- block reduction (256 threads) ----------------
__device__ __forceinline__ float blockReduceSum256(float val) {
    __shared__ float s[8];
    __shared__ float res;
    int lane = threadIdx.x & 31, w = threadIdx.x >> 5;
    #pragma unroll
    for (int o = 16; o; o >>= 1) val += __shfl_xor_sync(0xffffffffu, val, o);
    if (lane == 0) s[w] = val;
    __syncthreads();
    if (threadIdx.x < 8) {
        float v = s[threadIdx.x];
        #pragma unroll
        for (int o = 4; o; o >>= 1) v += __shfl_xor_sync(0xffu, v, o);
        if (threadIdx.x == 0) res = v;
    }
    __syncthreads();
    float r = res;
    __syncthreads();   // protect res/s from next call's writes
    return r;
}

// ---------------- RoPE tables (fp32 pipeline matching jax) ----------------
__global__ void rope_table_kernel() {
    long idx = (long)blockIdx.x * blockDim.x + threadIdx.x;
    if (idx >= (long)TT * KK) return;
    int t = (int)(idx / KK);
    int k = (int)(idx % KK);
    int i = k & (KK / 2 - 1);
    float ex  = (2.0f * (float)i) / (float)KK;
    float inv = 1.0f / powf(10000.0f, ex);
    float th  = (float)t * inv;
    g_cos[idx] = cosf(th);
    g_sin[idx] = sinf(th);
}

// ---------------- embedding gather + LayerNorm ----------------
__global__ void embed_ln_kernel(const int* __restrict__ input_,
                                const float* __restrict__ emb) {
    int row = blockIdx.x;                 // B*T rows
    int tok = input_[row];
    float x = emb[(long)tok * DD + threadIdx.x];
    float mu = blockReduceSum256(x) * (1.0f / DD);
    float d = x - mu;
    float var = blockReduceSum256(d * d) * (1.0f / DD);
    g_v[(long)row * DD + threadIdx.x] = d * rsqrtf(var + EPS);
}

// ---------------- v += pos ----------------
__global__ void addpos_kernel(const float* __restrict__ pos) {
    long idx = (long)blockIdx.x * blockDim.x + threadIdx.x;   // B*T*D
    if (idx >= (long)BB * TT * DD) return;
    g_v[idx] += pos[idx % ((long)TT * DD)];
}

// ---------------- RoPE apply: q = x*cos + rot(x)*sin ----------------
__global__ void rope_apply_kernel() {
    long idx = (long)blockIdx.x * blockDim.x + threadIdx.x;  // B*H*T*K
    int k = (int)(idx & (KK - 1));
    int t = (int)((idx >> 10) & (TT - 1));
    float xv = g_x[idx];
    float other = (k < KK / 2) ? -g_x[idx + KK / 2] : g_x[idx - KK / 2];
    long tk = (long)t * KK + k;
    g_q[idx] = xv * g_cos[tk] + other * g_sin[tk];
}

// ---------------- generic row LayerNorm (in place), D=256 ----------------
__global__ void ln_rows_kernel(float* __restrict__ buf) {
    long row = blockIdx.x;
    float x = buf[row * DD + threadIdx.x];
    float mu = blockReduceSum256(x) * (1.0f / DD);
    float d = x - mu;
    float var = blockReduceSum256(d * d) * (1.0f / DD);
    buf[row * DD + threadIdx.x] = d * rsqrtf(var + EPS);
}

// ---------------- v = ln(v + ln(yE)) ----------------
__global__ void combine_kernel() {
    long row = blockIdx.x;                // B*T rows
    float u = g_yE[row * DD + threadIdx.x];
    float mu = blockReduceSum256(u) * (1.0f / DD);
    float d = u - mu;
    float var = blockReduceSum256(d * d) * (1.0f / DD);
    float w = g_v[row * DD + threadIdx.x] + d * rsqrtf(var + EPS);
    float mu2 = blockReduceSum256(w) * (1.0f / DD);
    float d2 = w - mu2;
    float var2 = blockReduceSum256(d2 * d2) * (1.0f / DD);
    g_v[row * DD + threadIdx.x] = d2 * rsqrtf(var2 + EPS);
}

// ---------------- tiled SGEMM ----------------
// C[M,N] = A[M,K] * op(B);  op(B)=B [K,N] (NN) or B^T with B stored [N,K] (NT)
// EPI: 0 = none, 1 = relu, 2 = relu then * Gate
// batching: z -> (b = z/Hdim, h = z%Hdim); per-operand (b,h) strides.
#define BM 128
#define BN 128
#define BKC 16
#define TM 8
#define TN 8

template<bool TRANSB, int EPI>
__global__ void __launch_bounds__(256, 2)
sgemm_kernel(const float* __restrict__ A, const float* __restrict__ B,
             float* __restrict__ C, const float* __restrict__ G,
             int M, int N, int Kd, int lda, int ldb, int ldc, int ldg,
             long sAb, long sAh, long sBb, long sBh,
             long sCb, long sCh, long sGb, long sGh, int Hdim)
{
    __shared__ float As[BKC][BM + 4];
    __shared__ float Bs[BKC][BN + 4];

    int z = blockIdx.z;
    int bb = z / Hdim, hh = z % Hdim;
    A += bb * sAb + hh * sAh;
    B += bb * sBb + hh * sBh;
    C += bb * sCb + hh * sCh;
    if (EPI == 2) G += bb * sGb + hh * sGh;

    int m0 = blockIdx.y * BM;
    int n0 = blockIdx.x * BN;
    int tid = threadIdx.x;
    int tx = tid & 15, ty = tid >> 4;

    float acc[TM][TN];
    #pragma unroll
    for (int i = 0; i < TM; i++)
        #pragma unroll
        for (int j = 0; j < TN; j++) acc[i][j] = 0.0f;

    for (int k0 = 0; k0 < Kd; k0 += BKC) {
        // load A tile (128 x 16), transpose into As[k][m]
        #pragma unroll
        for (int i = 0; i < 2; i++) {
            int p = tid + i * 256;
            int row = p >> 2;
            int c4  = (p & 3) * 4;
            float4 va = *reinterpret_cast<const float4*>(
                &A[(long)(m0 + row) * lda + k0 + c4]);
            As[c4 + 0][row] = va.x;
            As[c4 + 1][row] = va.y;
            As[c4 + 2][row] = va.z;
            As[c4 + 3][row] = va.w;
        }
        // load B tile
        if (!TRANSB) {
            #pragma unroll
            for (int i = 0; i < 2; i++) {
                int p = tid + i * 256;
                int row = p >> 5;
                int c4  = (p & 31) * 4;
                float4 vb = *reinterpret_cast<const float4*>(
                    &B[(long)(k0 + row) * ldb + n0 + c4]);
                *reinterpret_cast<float4*>(&Bs[row][c4]) = vb;
            }
        } else {
            #pragma unroll
            for (int i = 0; i < 2; i++) {
                int p = tid + i * 256;
                int nrow = p >> 2;
                int c4   = (p & 3) * 4;
                float4 vb = *reinterpret_cast<const float4*>(
                    &B[(long)(n0 + nrow) * ldb + k0 + c4]);
                Bs[c4 + 0][nrow] = vb.x;
                Bs[c4 + 1][nrow] = vb.y;
                Bs[c4 + 2][nrow] = vb.z;
                Bs[c4 + 3][nrow] = vb.w;
            }
        }
        __syncthreads();

        #pragma unroll
        for (int k = 0; k < BKC; k++) {
            float ra[TM], rb[TN];
            #pragma unroll
            for (int j = 0; j < TM; j++) ra[j] = As[k][ty * TM + j];
            #pragma unroll
            for (int j = 0; j < TN; j++) rb[j] = Bs[k][tx * TN + j];
            #pragma unroll
            for (int i = 0; i < TM; i++)
                #pragma unroll
                for (int j = 0; j < TN; j++)
                    acc[i][j] = fmaf(ra[i], rb[j], acc[i][j]);
        }
        __syncthreads();
    }

    // epilogue
    #pragma unroll
    for (int i = 0; i < TM; i++) {
        long cm = m0 + ty * TM + i;
        #pragma unroll
        for (int j = 0; j < TN; j += 4) {
            int cn = n0 + tx * TN + j;
            float4 r = make_float4(acc[i][j], acc[i][j+1], acc[i][j+2], acc[i][j+3]);
            if (EPI >= 1) {
                r.x = fmaxf(r.x, 0.f); r.y = fmaxf(r.y, 0.f);
                r.z = fmaxf(r.z, 0.f); r.w = fmaxf(r.w, 0.f);
            }
            if (EPI == 2) {
                float4 gv = *reinterpret_cast<const float4*>(&G[cm * ldg + cn]);
                r.x *= gv.x; r.y *= gv.y; r.z *= gv.z; r.w *= gv.w;
            }
            *reinterpret_cast<float4*>(&C[cm * (long)ldc + cn]) = r;
        }
    }
}

// ---------------- host launch ----------------
extern "C" void kernel_launch(void* const* d_in, const int* in_sizes, int n_in,
                              void* d_out, int out_size) {
    const int*   input_  = (const int*)d_in[0];
    const float* emb     = (const float*)d_in[1];
    const float* pos     = (const float*)d_in[2];
    const float* Dx      = (const float*)d_in[3];
    const float* Dy      = (const float*)d_in[4];
    const float* E       = (const float*)d_in[5];
    const float* readout = (const float*)d_in[6];
    float* out = (float*)d_out;

    float *v, *x, *q, *sc, *a, *y, *yE;
    cudaGetSymbolAddress((void**)&v,  g_v);
    cudaGetSymbolAddress((void**)&x,  g_x);
    cudaGetSymbolAddress((void**)&q,  g_q);
    cudaGetSymbolAddress((void**)&sc, g_scores);
    cudaGetSymbolAddress((void**)&a,  g_a);
    cudaGetSymbolAddress((void**)&y,  g_y);
    cudaGetSymbolAddress((void**)&yE, g_yE);

    const long TD = (long)TT * DD;      // 524288
    const long TK = (long)TT * KK;      // 2097152
    const long TTl = (long)TT * TT;     // 4194304
    const long TN_ = (long)TT * NN_;    // 8388608

    // RoPE tables (recomputed each call; deterministic)
    rope_table_kernel<<<(TT * KK + 255) / 256, 256>>>();

    // v = ln(emb[input])
    embed_ln_kernel<<<BB * TT, 256>>>(input_, emb);

    for (int l = 0; l < LL; l++) {
        // v += pos
        addpos_kernel<<<(BB * TT * DD + 255) / 256, 256>>>(pos);

        // x[b,h] = relu(v_b @ Dx_h) : M=2048 N=1024 K=256, z=8
        sgemm_kernel<false, 1><<<dim3(KK / BN, TT / BM, BB * HH), 256>>>(
            v, Dx, x, nullptr,
            TT, KK, DD, DD, KK, KK, 0,
            TD, 0, 0, (long)DD * KK, (long)HH * TK, TK, 0, 0, HH);

        // q = rope(x)
        rope_apply_kernel<<<(int)((long)BB * HH * TT * KK / 256), 256>>>();

        // scores[b,h] = q_bh @ q_bh^T : M=N=2048 K=1024
        sgemm_kernel<true, 0><<<dim3(TT / BN, TT / BM, BB * HH), 256>>>(
            q, q, sc, nullptr,
            TT, TT, KK, KK, KK, TT, 0,
            (long)HH * TK, TK, (long)HH * TK, TK, (long)HH * TTl, TTl, 0, 0, HH);

        // a[b,h] = scores_bh @ v_b : M=2048 N=256 K=2048
        sgemm_kernel<false, 0><<<dim3(DD / BN, TT / BM, BB * HH), 256>>>(
            sc, v, a, nullptr,
            TT, DD, TT, TT, DD, DD, 0,
            (long)HH * TTl, TTl, TD, 0, (long)HH * TD, TD, 0, 0, HH);

        // a = ln(a) row-wise
        ln_rows_kernel<<<BB * HH * TT, 256>>>(a);

        // y[b, t, h*K + k] = relu(ln(a)_bh @ Dy_h) * x[b,h,t,k]
        sgemm_kernel<false, 2><<<dim3(KK / BN, TT / BM, BB * HH), 256>>>(
            a, Dy, y, x,
            TT, KK, DD, DD, KK, NN_, KK,
            (long)HH * TD, TD, 0, (long)DD * KK,
            TN_, (long)KK, (long)HH * TK, TK, HH);

        // yE = y @ E : M = B*T = 4096, N=256, K=4096
        sgemm_kernel<false, 0><<<dim3(DD / BN, (BB * TT) / BM, 1), 256>>>(
            y, E, yE, nullptr,
            BB * TT, DD, NN_, NN_, DD, DD, 0,
            0, 0, 0, 0, 0, 0, 0, 0, 1);

        // v = ln(v + ln(yE))
        combine_kernel<<<BB * TT, 256>>>();
    }

    // out = v @ readout : M=4096 N=32000 K=256
    sgemm_kernel<false, 0><<<dim3(BV / BN, (BB * TT) / BM, 1), 256>>>(
        v, readout, out, nullptr,
        BB * TT, BV, DD, DD, BV, BV, 0,
        0, 0, 0, 0, 0, 0, 0, 0, 1);
}

// round 4
// speedup vs baseline: 1.9193x; 1.9193x over previous
#include <cuda_runtime.h>
#include <cuda_bf16.h>
#include <math.h>
#include <stdint.h>

// ---------------- problem constants ----------------
#define BV   32000
#define TT   2048
#define HH   4
#define NN_  4096
#define DD   256
#define LL   6
#define KK   1024
#define BB   2
#define EPS  1e-5f

// ---------------- device scratch (no mallocs allowed) ----------------
__device__ float          g_v   [4096L*256];
__device__ __nv_bfloat16  g_v2a [4096L*512];     // [B*T, 2D] hi|lo
__device__ __nv_bfloat16  g_vT2 [2L*256*4096];   // [B][D, 2T]
__device__ float          g_x   [8L*2048*1024];  // [B,H,T,K] fp32
__device__ __nv_bfloat16  g_q2  [8L*2048*2048];  // [B,H,T,2K]
__device__ __nv_bfloat16  g_s2  [8L*2048*4096];  // [B,H,T,2T]
__device__ float          g_a   [8L*2048*256];
__device__ __nv_bfloat16  g_a2  [8L*2048*512];
__device__ __nv_bfloat16  g_y2  [2L*2048*8192];  // [B,T,2N]
__device__ float          g_yE  [4096L*256];
__device__ __nv_bfloat16  g_Dx2 [4L*1024*512];   // [H][K, 2D]
__device__ __nv_bfloat16  g_Dy2 [4L*1024*512];
__device__ __nv_bfloat16  g_E2  [256L*8192];     // [D, 2N]
__device__ __nv_bfloat16  g_ro2 [32000L*512];    // [V, 2D]
__device__ float          g_cos [2048L*1024];
__device__ float          g_sin [2048L*1024];

// ---------------- PTX helpers (baseline ISA only: sm_80-class) ----------------
__device__ __forceinline__ uint32_t smem_u32(const void* p) {
    uint32_t a;
    asm("{ .reg .u64 t; cvta.to.shared.u64 t, %1; cvt.u32.u64 %0, t; }" : "=r"(a) : "l"(p));
    return a;
}
#define CP_ASYNC16(saddr, gaddr) \
    asm volatile("cp.async.cg.shared.global [%0], [%1], 16;" :: "r"(saddr), "l"(gaddr))
#define CP_COMMIT() asm volatile("cp.async.commit_group;" ::: "memory")
#define CP_WAIT2()  asm volatile("cp.async.wait_group 2;" ::: "memory")

#define LDSM_X4(r0, r1, r2, r3, addr) \
    asm volatile("ldmatrix.sync.aligned.m8n8.x4.shared.b16 {%0,%1,%2,%3}, [%4];" \
        : "=r"(r0), "=r"(r1), "=r"(r2), "=r"(r3) : "r"(addr))

#define MMA16816(d, a, b0, b1) \
    asm volatile("mma.sync.aligned.m16n8k16.row.col.f32.bf16.bf16.f32 " \
        "{%0,%1,%2,%3}, {%4,%5,%6,%7}, {%8,%9}, {%0,%1,%2,%3};" \
        : "+f"((d)[0]), "+f"((d)[1]), "+f"((d)[2]), "+f"((d)[3]) \
        : "r"((a)[0]), "r"((a)[1]), "r"((a)[2]), "r"((a)[3]), "r"(b0), "r"(b1))

__device__ __forceinline__ void split2(float f, __nv_bfloat16& h, __nv_bfloat16& l) {
    h = __float2bfloat16(f);
    l = __float2bfloat16(f - __bfloat162float(h));
}

// ---------------- block reduction (256 threads) ----------------
__device__ __forceinline__ float blockReduceSum256(float val) {
    __shared__ float s[8];
    __shared__ float res;
    int lane = threadIdx.x & 31, w = threadIdx.x >> 5;
    #pragma unroll
    for (int o = 16; o; o >>= 1) val += __shfl_xor_sync(0xffffffffu, val, o);
    if (lane == 0) s[w] = val;
    __syncthreads();
    if (threadIdx.x < 8) {
        float v = s[threadIdx.x];
        #pragma unroll
        for (int o = 4; o; o >>= 1) v += __shfl_xor_sync(0xffu, v, o);
        if (threadIdx.x == 0) res = v;
    }
    __syncthreads();
    float r = res;
    __syncthreads();
    return r;
}

// ---------------- elementwise kernels ----------------
__global__ void rope_table_kernel() {
    long idx = (long)blockIdx.x * blockDim.x + threadIdx.x;
    if (idx >= (long)TT * KK) return;
    int t = (int)(idx / KK);
    int k = (int)(idx % KK);
    int i = k & (KK / 2 - 1);
    float ex  = (2.0f * (float)i) / (float)KK;
    float inv = 1.0f / powf(10000.0f, ex);
    float th  = (float)t * inv;
    g_cos[idx] = cosf(th);
    g_sin[idx] = sinf(th);
}

__global__ void embed_ln_kernel(const int* __restrict__ input_,
                                const float* __restrict__ emb) {
    int row = blockIdx.x;
    int tok = input_[row];
    float x = emb[(long)tok * DD + threadIdx.x];
    float mu = blockReduceSum256(x) * (1.0f / DD);
    float d = x - mu;
    float var = blockReduceSum256(d * d) * (1.0f / DD);
    g_v[(long)row * DD + threadIdx.x] = d * rsqrtf(var + EPS);
}

__global__ void addpos_split_kernel(const float* __restrict__ pos) {
    int row = blockIdx.x;                  // B*T
    int t = row & (TT - 1);
    int d = threadIdx.x;
    long o = (long)row * DD + d;
    float f = g_v[o] + pos[(long)t * DD + d];
    g_v[o] = f;
    __nv_bfloat16 h, l; split2(f, h, l);
    g_v2a[(long)row * 2 * DD + d] = h;
    g_v2a[(long)row * 2 * DD + DD + d] = l;
}

__global__ void combine_split_kernel() {
    long row = blockIdx.x;                 // B*T
    float u = g_yE[row * DD + threadIdx.x];
    float mu = blockReduceSum256(u) * (1.0f / DD);
    float d = u - mu;
    float var = blockReduceSum256(d * d) * (1.0f / DD);
    float w = g_v[row * DD + threadIdx.x] + d * rsqrtf(var + EPS);
    float mu2 = blockReduceSum256(w) * (1.0f / DD);
    float d2 = w - mu2;
    float var2 = blockReduceSum256(d2 * d2) * (1.0f / DD);
    float f = d2 * rsqrtf(var2 + EPS);
    g_v[row * DD + threadIdx.x] = f;
    __nv_bfloat16 h, l; split2(f, h, l);
    g_v2a[row * 2 * DD + threadIdx.x] = h;
    g_v2a[row * 2 * DD + DD + threadIdx.x] = l;
}

__global__ void ln_split_kernel() {
    long row = blockIdx.x;                 // B*H*T
    float x = g_a[row * DD + threadIdx.x];
    float mu = blockReduceSum256(x) * (1.0f / DD);
    float d = x - mu;
    float var = blockReduceSum256(d * d) * (1.0f / DD);
    float f = d * rsqrtf(var + EPS);
    __nv_bfloat16 h, l; split2(f, h, l);
    g_a2[row * 2 * DD + threadIdx.x] = h;
    g_a2[row * 2 * DD + DD + threadIdx.x] = l;
}

__global__ void rope_split_kernel() {
    long idx = (long)blockIdx.x * blockDim.x + threadIdx.x;  // B*H*T*K
    int k = (int)(idx & (KK - 1));
    long bht = idx >> 10;
    int t = (int)(bht & (TT - 1));
    float xv = g_x[idx];
    float other = (k < KK / 2) ? -g_x[idx + KK / 2] : g_x[idx - KK / 2];
    long tk = (long)t * KK + k;
    float qv = xv * g_cos[tk] + other * g_sin[tk];
    __nv_bfloat16 h, l; split2(qv, h, l);
    g_q2[bht * 2048 + k] = h;
    g_q2[bht * 2048 + KK + k] = l;
}

// X [R,C] fp32 -> Y [C, 2R] bf16 (hi cols [0,R), lo cols [R,2R))
__global__ void transpose_split_kernel(const float* __restrict__ X,
                                       __nv_bfloat16* __restrict__ Y,
                                       int R, int C, long inZ, long outZ) {
    __shared__ float tile[32][33];
    X += (long)blockIdx.z * inZ;
    Y += (long)blockIdx.z * outZ;
    int r0 = blockIdx.y * 32, c0 = blockIdx.x * 32;
    int tx = threadIdx.x, ty = threadIdx.y;   // (32,8)
    #pragma unroll
    for (int i = 0; i < 32; i += 8)
        tile[ty + i][tx] = X[(long)(r0 + ty + i) * C + c0 + tx];
    __syncthreads();
    #pragma unroll
    for (int i = 0; i < 32; i += 8) {
        float f = tile[tx][ty + i];           // X[r0+tx][c0+ty+i]
        __nv_bfloat16 h, l; split2(f, h, l);
        long orow = (long)(c0 + ty + i) * 2 * R;
        Y[orow + r0 + tx] = h;
        Y[orow + R + r0 + tx] = l;
    }
}

// ---------------- mma.sync GEMM (HMMA path; no sm_103a features) ----------------
// C[M,N] = A2[M,2K] x B2[N,2K]^T with bf16 hi/lo split (3 passes over K).
// CTA tile 128x128, K-chunk 32, 3-stage cp.async pipeline.
// 8 warps in 2(m) x 4(n), warp tile 64x32 via 4x4 m16n8k16.
// Smem per tile: 128 rows x 80B stride (64B data + pad) -> conflict-free ldmatrix.
// EPI: 0=fp32, 1=relu fp32, 2=split bf16 (hi at col, lo at col+loOff),
//      3=relu*G split bf16
#define STAGE_BYTES 20480            // A(10240) + B(10240)
#define SMEM_GEMM_BYTES (3 * STAGE_BYTES)

template<int EPI>
__global__ void __launch_bounds__(256, 2)
gemm_mma(const __nv_bfloat16* __restrict__ A, const __nv_bfloat16* __restrict__ B,
         void* __restrict__ Cv, const float* __restrict__ G,
         int Kd, int lda, int ldb, int ldc, int ldgt, int loOff,
         long sAb, long sAh, long sBb, long sBh, long sCb, long sCh,
         long sGb, long sGh, int Hdim)
{
    extern __shared__ char dsm[];
    uint32_t sbase = smem_u32(dsm);

    int tid = threadIdx.x;
    int lane = tid & 31;
    int wid = tid >> 5;
    int wm = wid >> 2;        // 0..1
    int wn = wid & 3;         // 0..3

    int z = blockIdx.z;
    int bb = z / Hdim, hh = z - bb * Hdim;
    A += bb * sAb + hh * sAh;
    B += bb * sBb + hh * sBh;
    long cOff = bb * sCb + hh * sCh;
    if (EPI == 3) G += bb * sGb + hh * sGh;

    int m0 = blockIdx.y * 128;
    int n0 = blockIdx.x * 128;

    const int KC = Kd >> 5;       // 32-wide chunks per pass
    const int nch = 3 * KC;

    // per-thread load slots: idx = tid + i*256 -> row=idx>>2 (0..127), seg=idx&3
    int lrow = tid >> 2;
    int lseg = tid & 3;

    auto issue = [&](int cc) {
        int p  = (cc < KC) ? 0 : ((cc < 2 * KC) ? 1 : 2);
        int kc = cc - p * KC;
        int aoff = ((p == 2) ? Kd : 0) + (kc << 5);
        int boff = ((p == 1) ? Kd : 0) + (kc << 5);
        uint32_t sa = sbase + (cc % 3) * STAGE_BYTES;
        uint32_t sb = sa + 10240;
        #pragma unroll
        for (int i = 0; i < 2; i++) {
            int row = lrow + i * 64;
            const __nv_bfloat16* ga = A + (long)(m0 + row) * lda + aoff + lseg * 8;
            const __nv_bfloat16* gb = B + (long)(n0 + row) * ldb + boff + lseg * 8;
            uint32_t da = sa + row * 80 + lseg * 16;
            uint32_t db = sb + row * 80 + lseg * 16;
            CP_ASYNC16(da, ga);
            CP_ASYNC16(db, gb);
        }
    };

    float acc[4][4][4];
    #pragma unroll
    for (int i = 0; i < 4; i++)
        #pragma unroll
        for (int j = 0; j < 4; j++)
            #pragma unroll
            for (int r = 0; r < 4; r++) acc[i][j][r] = 0.0f;

    issue(0); CP_COMMIT();
    issue(1); CP_COMMIT();

    int rsel = lane & 15;
    int chalf = (lane >> 4) * 16;   // byte offset within 32B k-halves

    for (int c = 0; c < nch; c++) {
        if (c + 2 < nch) issue(c + 2);
        CP_COMMIT();
        CP_WAIT2();
        __syncthreads();

        uint32_t sa = sbase + (c % 3) * STAGE_BYTES;
        uint32_t sb = sa + 10240;

        #pragma unroll
        for (int ks = 0; ks < 2; ks++) {
            int colb = ks * 32 + chalf;
            uint32_t ar[4][4], br[2][4];
            #pragma unroll
            for (int mt = 0; mt < 4; mt++) {
                uint32_t addr = sa + (uint32_t)(wm * 64 + mt * 16 + rsel) * 80u + colb;
                LDSM_X4(ar[mt][0], ar[mt][1], ar[mt][2], ar[mt][3], addr);
            }
            #pragma unroll
            for (int n2 = 0; n2 < 2; n2++) {
                uint32_t addr = sb + (uint32_t)(wn * 32 + n2 * 16 + rsel) * 80u + colb;
                LDSM_X4(br[n2][0], br[n2][1], br[n2][2], br[n2][3], addr);
            }
            #pragma unroll
            for (int mt = 0; mt < 4; mt++)
                #pragma unroll
                for (int nt = 0; nt < 4; nt++) {
                    int n2 = nt >> 1, j = nt & 1;
                    MMA16816(acc[mt][nt], ar[mt], br[n2][j], br[n2][2 + j]);
                }
        }
        __syncthreads();
    }

    // ---------------- epilogue ----------------
    int g = lane >> 2, tg = lane & 3;
    float* Cf = (float*)Cv;
    __nv_bfloat16* Cb = (__nv_bfloat16*)Cv;

    #pragma unroll
    for (int mt = 0; mt < 4; mt++) {
        #pragma unroll
        for (int half = 0; half < 2; half++) {
            long row = m0 + wm * 64 + mt * 16 + g + half * 8;
            #pragma unroll
            for (int nt = 0; nt < 4; nt++) {
                int co = n0 + wn * 32 + nt * 8 + tg * 2;
                float f0 = acc[mt][nt][half * 2 + 0];
                float f1 = acc[mt][nt][half * 2 + 1];
                if (EPI == 0) {
                    *reinterpret_cast<float2*>(&Cf[cOff + row * ldc + co]) =
                        make_float2(f0, f1);
                } else if (EPI == 1) {
                    *reinterpret_cast<float2*>(&Cf[cOff + row * ldc + co]) =
                        make_float2(fmaxf(f0, 0.f), fmaxf(f1, 0.f));
                } else {
                    if (EPI == 3) {
                        float2 gv = *reinterpret_cast<const float2*>(
                            &G[row * (long)ldgt + co]);
                        f0 = fmaxf(f0, 0.f) * gv.x;
                        f1 = fmaxf(f1, 0.f) * gv.y;
                    }
                    __nv_bfloat16 h0, l0, h1, l1;
                    split2(f0, h0, l0);
                    split2(f1, h1, l1);
                    uint32_t hp = (uint32_t)*(uint16_t*)&h0 |
                                  ((uint32_t)*(uint16_t*)&h1 << 16);
                    uint32_t lp = (uint32_t)*(uint16_t*)&l0 |
                                  ((uint32_t)*(uint16_t*)&l1 << 16);
                    *reinterpret_cast<uint32_t*>(&Cb[cOff + row * ldc + co]) = hp;
                    *reinterpret_cast<uint32_t*>(&Cb[cOff + row * ldc + co + loOff]) = lp;
                }
            }
        }
    }
}

// ---------------- host launch ----------------
extern "C" void kernel_launch(void* const* d_in, const int* in_sizes, int n_in,
                              void* d_out, int out_size) {
    const int*   input_  = (const int*)d_in[0];
    const float* emb     = (const float*)d_in[1];
    const float* pos     = (const float*)d_in[2];
    const float* Dx      = (const float*)d_in[3];
    const float* Dy      = (const float*)d_in[4];
    const float* E       = (const float*)d_in[5];
    const float* readout = (const float*)d_in[6];
    float* out = (float*)d_out;

    cudaFuncSetAttribute(gemm_mma<0>, cudaFuncAttributeMaxDynamicSharedMemorySize, SMEM_GEMM_BYTES);
    cudaFuncSetAttribute(gemm_mma<1>, cudaFuncAttributeMaxDynamicSharedMemorySize, SMEM_GEMM_BYTES);
    cudaFuncSetAttribute(gemm_mma<2>, cudaFuncAttributeMaxDynamicSharedMemorySize, SMEM_GEMM_BYTES);
    cudaFuncSetAttribute(gemm_mma<3>, cudaFuncAttributeMaxDynamicSharedMemorySize, SMEM_GEMM_BYTES);

    float *v, *x, *a, *yE;
    __nv_bfloat16 *v2a, *vT2, *q2, *s2, *a2, *y2, *Dx2, *Dy2, *E2, *ro2;
    cudaGetSymbolAddress((void**)&v,   g_v);
    cudaGetSymbolAddress((void**)&v2a, g_v2a);
    cudaGetSymbolAddress((void**)&vT2, g_vT2);
    cudaGetSymbolAddress((void**)&x,   g_x);
    cudaGetSymbolAddress((void**)&q2,  g_q2);
    cudaGetSymbolAddress((void**)&s2,  g_s2);
    cudaGetSymbolAddress((void**)&a,   g_a);
    cudaGetSymbolAddress((void**)&a2,  g_a2);
    cudaGetSymbolAddress((void**)&y2,  g_y2);
    cudaGetSymbolAddress((void**)&yE,  g_yE);
    cudaGetSymbolAddress((void**)&Dx2, g_Dx2);
    cudaGetSymbolAddress((void**)&Dy2, g_Dy2);
    cudaGetSymbolAddress((void**)&E2,  g_E2);
    cudaGetSymbolAddress((void**)&ro2, g_ro2);

    dim3 tb(32, 8);

    // Precompute tables + transposed/split weights
    rope_table_kernel<<<(TT * KK + 255) / 256, 256>>>();
    embed_ln_kernel<<<BB * TT, 256>>>(input_, emb);
    // Dx [H,D,K] -> Dx2 [H][K,2D]
    transpose_split_kernel<<<dim3(KK / 32, DD / 32, HH), tb>>>(Dx, Dx2, DD, KK, (long)DD * KK, (long)KK * 2 * DD);
    transpose_split_kernel<<<dim3(KK / 32, DD / 32, HH), tb>>>(Dy, Dy2, DD, KK, (long)DD * KK, (long)KK * 2 * DD);
    // E [N,D] -> E2 [D,2N]
    transpose_split_kernel<<<dim3(DD / 32, NN_ / 32, 1), tb>>>(E, E2, NN_, DD, 0, 0);
    // readout [D,V] -> ro2 [V,2D]
    transpose_split_kernel<<<dim3(BV / 32, DD / 32, 1), tb>>>(readout, ro2, DD, BV, 0, 0);

    const long TK  = (long)TT * KK;
    const long T2D = (long)TT * 2 * DD;
    const long T2K = (long)TT * 2 * KK;
    const long T2T = (long)TT * 2 * TT;
    const long T2N = (long)TT * 2 * NN_;
    const long TD  = (long)TT * DD;

    for (int l = 0; l < LL; l++) {
        addpos_split_kernel<<<BB * TT, 256>>>(pos);
        // v [b][T,D] -> vT2 [b][D,2T]
        transpose_split_kernel<<<dim3(DD / 32, TT / 32, BB), tb>>>(v, vT2, TT, DD, TD, (long)DD * 2 * TT);

        // x[b,h] = relu(v2a_b @ Dx2_h^T)  fp32 : M=2048 N=1024 Kd=256
        gemm_mma<1><<<dim3(KK / 128, TT / 128, BB * HH), 256, SMEM_GEMM_BYTES>>>(
            v2a, Dx2, x, nullptr,
            DD, 2 * DD, 2 * DD, KK, 0, 0,
            T2D, 0, 0, (long)KK * 2 * DD, (long)HH * TK, TK, 0, 0, HH);

        rope_split_kernel<<<(int)((long)BB * HH * TT * KK / 256), 256>>>();

        // s2[b,h] = q2 @ q2^T (split out) : M=N=2048 Kd=1024, loOff=2048
        gemm_mma<2><<<dim3(TT / 128, TT / 128, BB * HH), 256, SMEM_GEMM_BYTES>>>(
            q2, q2, s2, nullptr,
            KK, 2 * KK, 2 * KK, 2 * TT, 0, TT,
            (long)HH * T2K, T2K, (long)HH * T2K, T2K, (long)HH * T2T, T2T, 0, 0, HH);

        // a[b,h] = s2 @ vT2^T fp32 : M=2048 N=256 Kd=2048
        gemm_mma<0><<<dim3(DD / 128, TT / 128, BB * HH), 256, SMEM_GEMM_BYTES>>>(
            s2, vT2, a, nullptr,
            TT, 2 * TT, 2 * TT, DD, 0, 0,
            (long)HH * T2T, T2T, (long)DD * 2 * TT, 0, (long)HH * TD, TD, 0, 0, HH);

        ln_split_kernel<<<BB * HH * TT, 256>>>();

        // y2[b, t, h*K+n] = relu(a2 @ Dy2^T) * x  (split, loOff=NN_)
        gemm_mma<3><<<dim3(KK / 128, TT / 128, BB * HH), 256, SMEM_GEMM_BYTES>>>(
            a2, Dy2, y2, x,
            DD, 2 * DD, 2 * DD, 2 * NN_, KK, NN_,
            (long)HH * T2D, T2D, 0, (long)KK * 2 * DD,
            T2N, (long)KK, (long)HH * TK, TK, HH);

        // yE = y2 @ E2^T fp32 : M=4096 N=256 Kd=4096
        gemm_mma<0><<<dim3(DD / 128, (BB * TT) / 128, 1), 256, SMEM_GEMM_BYTES>>>(
            y2, E2, yE, nullptr,
            NN_, 2 * NN_, 2 * NN_, DD, 0, 0,
            0, 0, 0, 0, 0, 0, 0, 0, 1);

        combine_split_kernel<<<BB * TT, 256>>>();
    }

    // out = v2a @ ro2^T fp32 : M=4096 N=32000 Kd=256
    gemm_mma<0><<<dim3(BV / 128, (BB * TT) / 128, 1), 256, SMEM_GEMM_BYTES>>>(
        v2a, ro2, out, nullptr,
        DD, 2 * DD, 2 * DD, BV, 0, 0,
        0, 0, 0, 0, 0, 0, 0, 0, 1);
}

// round 5
// speedup vs baseline: 2.5767x; 1.3425x over previous
#include <cuda_runtime.h>
#include <cuda_bf16.h>
#include <math.h>
#include <stdint.h>

// ---------------- problem constants ----------------
#define BV   32000
#define TT   2048
#define HH   4
#define NN_  4096
#define DD   256
#define LL   6
#define KK   1024
#define BB   2
#define EPS  1e-5f

// ---------------- device scratch (no mallocs allowed) ----------------
__device__ float          g_v   [4096L*256];
__device__ __nv_bfloat16  g_v2a [4096L*512];     // [B*T, 2D] hi|lo
__device__ __nv_bfloat16  g_vT2 [2L*256*4096];   // [B][D, 2T]
__device__ float          g_x   [8L*2048*1024];  // [B,H,T,K] fp32
__device__ __nv_bfloat16  g_q2  [8L*2048*2048];  // [B,H,T,2K]
__device__ __nv_bfloat16  g_s2  [8L*2048*4096];  // [B,H,T,2T]
__device__ float          g_a   [8L*2048*256];
__device__ __nv_bfloat16  g_a2  [8L*2048*512];
__device__ __nv_bfloat16  g_y2  [2L*2048*8192];  // [B,T,2N]
__device__ float          g_yE  [2L*4096*256];   // 2 split-K partials
__device__ __nv_bfloat16  g_Dx2 [4L*1024*512];   // [H][K, 2D]
__device__ __nv_bfloat16  g_Dy2 [4L*1024*512];
__device__ __nv_bfloat16  g_E2  [256L*8192];     // [D, 2N]
__device__ __nv_bfloat16  g_ro2 [32000L*512];    // [V, 2D]
__device__ float          g_cos [2048L*1024];
__device__ float          g_sin [2048L*1024];

// ---------------- PTX helpers (baseline ISA only: sm_80-class) ----------------
__device__ __forceinline__ uint32_t smem_u32(const void* p) {
    uint32_t a;
    asm("{ .reg .u64 t; cvta.to.shared.u64 t, %1; cvt.u32.u64 %0, t; }" : "=r"(a) : "l"(p));
    return a;
}
#define CP_ASYNC16(saddr, gaddr) \
    asm volatile("cp.async.cg.shared.global [%0], [%1], 16;" :: "r"(saddr), "l"(gaddr))
#define CP_COMMIT() asm volatile("cp.async.commit_group;" ::: "memory")
#define CP_WAIT2()  asm volatile("cp.async.wait_group 2;" ::: "memory")
#define CP_WAIT0()  asm volatile("cp.async.wait_group 0;" ::: "memory")

#define LDSM_X4(r0, r1, r2, r3, addr) \
    asm volatile("ldmatrix.sync.aligned.m8n8.x4.shared.b16 {%0,%1,%2,%3}, [%4];" \
        : "=r"(r0), "=r"(r1), "=r"(r2), "=r"(r3) : "r"(addr))

#define MMA16816(d, a, b0, b1) \
    asm volatile("mma.sync.aligned.m16n8k16.row.col.f32.bf16.bf16.f32 " \
        "{%0,%1,%2,%3}, {%4,%5,%6,%7}, {%8,%9}, {%0,%1,%2,%3};" \
        : "+f"((d)[0]), "+f"((d)[1]), "+f"((d)[2]), "+f"((d)[3]) \
        : "r"((a)[0]), "r"((a)[1]), "r"((a)[2]), "r"((a)[3]), "r"(b0), "r"(b1))

__device__ __forceinline__ void split2(float f, __nv_bfloat16& h, __nv_bfloat16& l) {
    h = __float2bfloat16(f);
    l = __float2bfloat16(f - __bfloat162float(h));
}

// ---------------- block reduction (256 threads) ----------------
__device__ __forceinline__ float blockReduceSum256(float val) {
    __shared__ float s[8];
    __shared__ float res;
    int lane = threadIdx.x & 31, w = threadIdx.x >> 5;
    #pragma unroll
    for (int o = 16; o; o >>= 1) val += __shfl_xor_sync(0xffffffffu, val, o);
    if (lane == 0) s[w] = val;
    __syncthreads();
    if (threadIdx.x < 8) {
        float v = s[threadIdx.x];
        #pragma unroll
        for (int o = 4; o; o >>= 1) v += __shfl_xor_sync(0xffu, v, o);
        if (threadIdx.x == 0) res = v;
    }
    __syncthreads();
    float r = res;
    __syncthreads();
    return r;
}

// ---------------- elementwise kernels ----------------
__global__ void rope_table_kernel() {
    long idx = (long)blockIdx.x * blockDim.x + threadIdx.x;
    if (idx >= (long)TT * KK) return;
    int t = (int)(idx / KK);
    int k = (int)(idx % KK);
    int i = k & (KK / 2 - 1);
    float ex  = (2.0f * (float)i) / (float)KK;
    float inv = 1.0f / powf(10000.0f, ex);
    float th  = (float)t * inv;
    g_cos[idx] = cosf(th);
    g_sin[idx] = sinf(th);
}

__global__ void embed_ln_kernel(const int* __restrict__ input_,
                                const float* __restrict__ emb) {
    int row = blockIdx.x;
    int tok = input_[row];
    float x = emb[(long)tok * DD + threadIdx.x];
    float mu = blockReduceSum256(x) * (1.0f / DD);
    float d = x - mu;
    float var = blockReduceSum256(d * d) * (1.0f / DD);
    g_v[(long)row * DD + threadIdx.x] = d * rsqrtf(var + EPS);
}

__global__ void addpos_split_kernel(const float* __restrict__ pos) {
    int row = blockIdx.x;                  // B*T
    int t = row & (TT - 1);
    int d = threadIdx.x;
    long o = (long)row * DD + d;
    float f = g_v[o] + pos[(long)t * DD + d];
    g_v[o] = f;
    __nv_bfloat16 h, l; split2(f, h, l);
    g_v2a[(long)row * 2 * DD + d] = h;
    g_v2a[(long)row * 2 * DD + DD + d] = l;
}

__global__ void combine_split_kernel() {
    long row = blockIdx.x;                 // B*T
    float u = g_yE[row * DD + threadIdx.x] +
              g_yE[4096L * 256 + row * DD + threadIdx.x];
    float mu = blockReduceSum256(u) * (1.0f / DD);
    float d = u - mu;
    float var = blockReduceSum256(d * d) * (1.0f / DD);
    float w = g_v[row * DD + threadIdx.x] + d * rsqrtf(var + EPS);
    float mu2 = blockReduceSum256(w) * (1.0f / DD);
    float d2 = w - mu2;
    float var2 = blockReduceSum256(d2 * d2) * (1.0f / DD);
    float f = d2 * rsqrtf(var2 + EPS);
    g_v[row * DD + threadIdx.x] = f;
    __nv_bfloat16 h, l; split2(f, h, l);
    g_v2a[row * 2 * DD + threadIdx.x] = h;
    g_v2a[row * 2 * DD + DD + threadIdx.x] = l;
}

__global__ void ln_split_kernel() {
    long row = blockIdx.x;                 // B*H*T
    float x = g_a[row * DD + threadIdx.x];
    float mu = blockReduceSum256(x) * (1.0f / DD);
    float d = x - mu;
    float var = blockReduceSum256(d * d) * (1.0f / DD);
    float f = d * rsqrtf(var + EPS);
    __nv_bfloat16 h, l; split2(f, h, l);
    g_a2[row * 2 * DD + threadIdx.x] = h;
    g_a2[row * 2 * DD + DD + threadIdx.x] = l;
}

__global__ void rope_split_kernel() {
    long idx = (long)blockIdx.x * blockDim.x + threadIdx.x;  // B*H*T*K
    int k = (int)(idx & (KK - 1));
    long bht = idx >> 10;
    int t = (int)(bht & (TT - 1));
    float xv = g_x[idx];
    float other = (k < KK / 2) ? -g_x[idx + KK / 2] : g_x[idx - KK / 2];
    long tk = (long)t * KK + k;
    float qv = xv * g_cos[tk] + other * g_sin[tk];
    __nv_bfloat16 h, l; split2(qv, h, l);
    g_q2[bht * 2048 + k] = h;
    g_q2[bht * 2048 + KK + k] = l;
}

// X [R,C] fp32 -> Y [C, 2R] bf16 (hi cols [0,R), lo cols [R,2R))
__global__ void transpose_split_kernel(const float* __restrict__ X,
                                       __nv_bfloat16* __restrict__ Y,
                                       int R, int C, long inZ, long outZ) {
    __shared__ float tile[32][33];
    X += (long)blockIdx.z * inZ;
    Y += (long)blockIdx.z * outZ;
    int r0 = blockIdx.y * 32, c0 = blockIdx.x * 32;
    int tx = threadIdx.x, ty = threadIdx.y;   // (32,8)
    #pragma unroll
    for (int i = 0; i < 32; i += 8)
        tile[ty + i][tx] = X[(long)(r0 + ty + i) * C + c0 + tx];
    __syncthreads();
    #pragma unroll
    for (int i = 0; i < 32; i += 8) {
        float f = tile[tx][ty + i];           // X[r0+tx][c0+ty+i]
        __nv_bfloat16 h, l; split2(f, h, l);
        long orow = (long)(c0 + ty + i) * 2 * R;
        Y[orow + r0 + tx] = h;
        Y[orow + R + r0 + tx] = l;
    }
}

// ---------------- mma.sync GEMM (HMMA path) ----------------
// C[M,N] = A2[M,2K] x B2[N,2K]^T with bf16 hi/lo split (3 passes over K).
// CTA tile 128x128, K-chunk 32, 3-stage cp.async pipeline.
// 8 warps in 2(m) x 4(n), warp tile 64x32 via 4x4 m16n8k16.
// EPI: 0=fp32, 1=relu fp32, 2=split bf16 (hi at col, lo at col+loOff),
//      3=relu*G split bf16
// SYM: A==B, M==N==2048; blockIdx.x enumerates 136 upper-tri block pairs,
//      mirror tile written via smem transpose.
// Split-K: nsplit in {1,2}; z = blockIdx.z -> (sp = z%nsplit, batch = z/nsplit);
//      Kd is the per-split iterate size, KdLo the lo-region offset (= full Kd).
#define STAGE_BYTES 20480            // A(10240) + B(10240)
#define SMEM_GEMM_BYTES (3 * STAGE_BYTES)

template<int EPI, bool SYM>
__global__ void __launch_bounds__(256, 2)
gemm_mma(const __nv_bfloat16* __restrict__ A, const __nv_bfloat16* __restrict__ B,
         void* __restrict__ Cv, const float* __restrict__ G,
         int Kd, int KdLo, int lda, int ldb, int ldc, int ldgt, int loOff,
         long sAb, long sAh, long sBb, long sBh, long sCb, long sCh,
         long sGb, long sGh, int Hdim, int nsplit, long sSplitC)
{
    extern __shared__ char dsm[];
    uint32_t sbase = smem_u32(dsm);

    int tid = threadIdx.x;
    int lane = tid & 31;
    int wid = tid >> 5;
    int wm = wid >> 2;        // 0..1
    int wn = wid & 3;         // 0..3

    int zz = blockIdx.z;
    int sp = (nsplit > 1) ? (zz & 1) : 0;
    int z  = (nsplit > 1) ? (zz >> 1) : zz;
    int bb = z / Hdim, hh = z - bb * Hdim;
    A += bb * sAb + hh * sAh;
    B += bb * sBb + hh * sBh;
    long cOff = bb * sCb + hh * sCh + sp * sSplitC;
    if (EPI == 3) G += bb * sGb + hh * sGh;

    int m0, n0, diag = 0;
    if (SYM) {
        // 16x16 block grid of T=2048: upper triangle pairs
        int L = blockIdx.x, ii = 0;
        while (L >= 16 - ii) { L -= 16 - ii; ii++; }
        m0 = ii * 128; n0 = (ii + L) * 128;
        diag = (L == 0);
    } else {
        m0 = blockIdx.y * 128;
        n0 = blockIdx.x * 128;
    }

    const int KC = Kd >> 5;       // 32-wide chunks per pass
    const int nch = 3 * KC;
    const int spK = sp * Kd;

    int lrow = tid >> 2;
    int lseg = tid & 3;

    auto issue = [&](int cc) {
        int p  = (cc < KC) ? 0 : ((cc < 2 * KC) ? 1 : 2);
        int kc = cc - p * KC;
        int aoff = ((p == 2) ? KdLo : 0) + spK + (kc << 5);
        int boff = ((p == 1) ? KdLo : 0) + spK + (kc << 5);
        uint32_t sa = sbase + (cc % 3) * STAGE_BYTES;
        uint32_t sb = sa + 10240;
        #pragma unroll
        for (int i = 0; i < 2; i++) {
            int row = lrow + i * 64;
            const __nv_bfloat16* ga = A + (long)(m0 + row) * lda + aoff + lseg * 8;
            const __nv_bfloat16* gb = B + (long)(n0 + row) * ldb + boff + lseg * 8;
            uint32_t da = sa + row * 80 + lseg * 16;
            uint32_t db = sb + row * 80 + lseg * 16;
            CP_ASYNC16(da, ga);
            CP_ASYNC16(db, gb);
        }
    };

    float acc[4][4][4];
    #pragma unroll
    for (int i = 0; i < 4; i++)
        #pragma unroll
        for (int j = 0; j < 4; j++)
            #pragma unroll
            for (int r = 0; r < 4; r++) acc[i][j][r] = 0.0f;

    issue(0); CP_COMMIT();
    issue(1); CP_COMMIT();

    int rsel = lane & 15;
    int chalf = (lane >> 4) * 16;

    for (int c = 0; c < nch; c++) {
        if (c + 2 < nch) issue(c + 2);
        CP_COMMIT();
        CP_WAIT2();
        __syncthreads();

        uint32_t sa = sbase + (c % 3) * STAGE_BYTES;
        uint32_t sb = sa + 10240;

        #pragma unroll
        for (int ks = 0; ks < 2; ks++) {
            int colb = ks * 32 + chalf;
            uint32_t ar[4][4], br[2][4];
            #pragma unroll
            for (int mt = 0; mt < 4; mt++) {
                uint32_t addr = sa + (uint32_t)(wm * 64 + mt * 16 + rsel) * 80u + colb;
                LDSM_X4(ar[mt][0], ar[mt][1], ar[mt][2], ar[mt][3], addr);
            }
            #pragma unroll
            for (int n2 = 0; n2 < 2; n2++) {
                uint32_t addr = sb + (uint32_t)(wn * 32 + n2 * 16 + rsel) * 80u + colb;
                LDSM_X4(br[n2][0], br[n2][1], br[n2][2], br[n2][3], addr);
            }
            #pragma unroll
            for (int mt = 0; mt < 4; mt++)
                #pragma unroll
                for (int nt = 0; nt < 4; nt++) {
                    int n2 = nt >> 1, j = nt & 1;
                    MMA16816(acc[mt][nt], ar[mt], br[n2][j], br[n2][2 + j]);
                }
        }
        __syncthreads();
    }

    // ---------------- epilogue ----------------
    int g = lane >> 2, tg = lane & 3;
    float* Cf = (float*)Cv;
    __nv_bfloat16* Cb = (__nv_bfloat16*)Cv;

    #pragma unroll
    for (int mt = 0; mt < 4; mt++) {
        #pragma unroll
        for (int half = 0; half < 2; half++) {
            long row = m0 + wm * 64 + mt * 16 + g + half * 8;
            #pragma unroll
            for (int nt = 0; nt < 4; nt++) {
                int co = n0 + wn * 32 + nt * 8 + tg * 2;
                float f0 = acc[mt][nt][half * 2 + 0];
                float f1 = acc[mt][nt][half * 2 + 1];
                if (EPI == 0) {
                    *reinterpret_cast<float2*>(&Cf[cOff + row * ldc + co]) =
                        make_float2(f0, f1);
                } else if (EPI == 1) {
                    *reinterpret_cast<float2*>(&Cf[cOff + row * ldc + co]) =
                        make_float2(fmaxf(f0, 0.f), fmaxf(f1, 0.f));
                } else {
                    if (EPI == 3) {
                        float2 gv = *reinterpret_cast<const float2*>(
                            &G[row * (long)ldgt + co]);
                        f0 = fmaxf(f0, 0.f) * gv.x;
                        f1 = fmaxf(f1, 0.f) * gv.y;
                    }
                    __nv_bfloat16 h0, l0, h1, l1;
                    split2(f0, h0, l0);
                    split2(f1, h1, l1);
                    uint32_t hp = (uint32_t)*(uint16_t*)&h0 |
                                  ((uint32_t)*(uint16_t*)&h1 << 16);
                    uint32_t lp = (uint32_t)*(uint16_t*)&l0 |
                                  ((uint32_t)*(uint16_t*)&l1 << 16);
                    *reinterpret_cast<uint32_t*>(&Cb[cOff + row * ldc + co]) = hp;
                    *reinterpret_cast<uint32_t*>(&Cb[cOff + row * ldc + co + loOff]) = lp;
                }
            }
        }
    }

    // mirror tile C[n,m] = C[m,n] via smem transpose (coalesced stores)
    if (SYM && !diag) {
        CP_WAIT0();
        __syncthreads();
        __nv_bfloat16* sm = (__nv_bfloat16*)dsm;   // 128 x 144 bf16
        #pragma unroll
        for (int ph = 0; ph < 2; ph++) {
            #pragma unroll
            for (int mt = 0; mt < 4; mt++)
                #pragma unroll
                for (int half = 0; half < 2; half++) {
                    int r = wm * 64 + mt * 16 + g + half * 8;
                    #pragma unroll
                    for (int nt = 0; nt < 4; nt++) {
                        int cc = wn * 32 + nt * 8 + tg * 2;
                        float f0 = acc[mt][nt][half * 2 + 0];
                        float f1 = acc[mt][nt][half * 2 + 1];
                        __nv_bfloat16 h0, l0, h1, l1;
                        split2(f0, h0, l0);
                        split2(f1, h1, l1);
                        sm[cc * 144 + r]       = ph ? l0 : h0;
                        sm[(cc + 1) * 144 + r] = ph ? l1 : h1;
                    }
                }
            __syncthreads();
            int cc2 = tid >> 1, seg = (tid & 1) * 64;
            const uint4* src = (const uint4*)(sm + cc2 * 144 + seg);
            uint4* dst = (uint4*)(&Cb[cOff + (long)(n0 + cc2) * ldc + m0 + seg +
                                      (ph ? loOff : 0)]);
            #pragma unroll
            for (int u = 0; u < 8; u++) dst[u] = src[u];
            __syncthreads();
        }
    }
}

// ---------------- host launch ----------------
extern "C" void kernel_launch(void* const* d_in, const int* in_sizes, int n_in,
                              void* d_out, int out_size) {
    const int*   input_  = (const int*)d_in[0];
    const float* emb     = (const float*)d_in[1];
    const float* pos     = (const float*)d_in[2];
    const float* Dx      = (const float*)d_in[3];
    const float* Dy      = (const float*)d_in[4];
    const float* E       = (const float*)d_in[5];
    const float* readout = (const float*)d_in[6];
    float* out = (float*)d_out;

    cudaFuncSetAttribute(gemm_mma<0, false>, cudaFuncAttributeMaxDynamicSharedMemorySize, SMEM_GEMM_BYTES);
    cudaFuncSetAttribute(gemm_mma<1, false>, cudaFuncAttributeMaxDynamicSharedMemorySize, SMEM_GEMM_BYTES);
    cudaFuncSetAttribute(gemm_mma<2, true>,  cudaFuncAttributeMaxDynamicSharedMemorySize, SMEM_GEMM_BYTES);
    cudaFuncSetAttribute(gemm_mma<3, false>, cudaFuncAttributeMaxDynamicSharedMemorySize, SMEM_GEMM_BYTES);

    float *v, *x, *a, *yE;
    __nv_bfloat16 *v2a, *vT2, *q2, *s2, *a2, *y2, *Dx2, *Dy2, *E2, *ro2;
    cudaGetSymbolAddress((void**)&v,   g_v);
    cudaGetSymbolAddress((void**)&v2a, g_v2a);
    cudaGetSymbolAddress((void**)&vT2, g_vT2);
    cudaGetSymbolAddress((void**)&x,   g_x);
    cudaGetSymbolAddress((void**)&q2,  g_q2);
    cudaGetSymbolAddress((void**)&s2,  g_s2);
    cudaGetSymbolAddress((void**)&a,   g_a);
    cudaGetSymbolAddress((void**)&a2,  g_a2);
    cudaGetSymbolAddress((void**)&y2,  g_y2);
    cudaGetSymbolAddress((void**)&yE,  g_yE);
    cudaGetSymbolAddress((void**)&Dx2, g_Dx2);
    cudaGetSymbolAddress((void**)&Dy2, g_Dy2);
    cudaGetSymbolAddress((void**)&E2,  g_E2);
    cudaGetSymbolAddress((void**)&ro2, g_ro2);

    dim3 tb(32, 8);

    rope_table_kernel<<<(TT * KK + 255) / 256, 256>>>();
    embed_ln_kernel<<<BB * TT, 256>>>(input_, emb);
    transpose_split_kernel<<<dim3(KK / 32, DD / 32, HH), tb>>>(Dx, Dx2, DD, KK, (long)DD * KK, (long)KK * 2 * DD);
    transpose_split_kernel<<<dim3(KK / 32, DD / 32, HH), tb>>>(Dy, Dy2, DD, KK, (long)DD * KK, (long)KK * 2 * DD);
    transpose_split_kernel<<<dim3(DD / 32, NN_ / 32, 1), tb>>>(E, E2, NN_, DD, 0, 0);
    transpose_split_kernel<<<dim3(BV / 32, DD / 32, 1), tb>>>(readout, ro2, DD, BV, 0, 0);

    const long TK  = (long)TT * KK;
    const long T2D = (long)TT * 2 * DD;
    const long T2K = (long)TT * 2 * KK;
    const long T2T = (long)TT * 2 * TT;
    const long T2N = (long)TT * 2 * NN_;
    const long TD  = (long)TT * DD;

    for (int l = 0; l < LL; l++) {
        addpos_split_kernel<<<BB * TT, 256>>>(pos);
        transpose_split_kernel<<<dim3(DD / 32, TT / 32, BB), tb>>>(v, vT2, TT, DD, TD, (long)DD * 2 * TT);

        // x[b,h] = relu(v2a_b @ Dx2_h^T) fp32 : M=2048 N=1024 Kd=256
        gemm_mma<1, false><<<dim3(KK / 128, TT / 128, BB * HH), 256, SMEM_GEMM_BYTES>>>(
            v2a, Dx2, x, nullptr,
            DD, DD, 2 * DD, 2 * DD, KK, 0, 0,
            T2D, 0, 0, (long)KK * 2 * DD, (long)HH * TK, TK, 0, 0, HH, 1, 0);

        rope_split_kernel<<<(int)((long)BB * HH * TT * KK / 256), 256>>>();

        // s2[b,h] = q2 @ q2^T (split out, SYMMETRIC) : 136 upper-tri blocks
        gemm_mma<2, true><<<dim3(136, 1, BB * HH), 256, SMEM_GEMM_BYTES>>>(
            q2, q2, s2, nullptr,
            KK, KK, 2 * KK, 2 * KK, 2 * TT, 0, TT,
            (long)HH * T2K, T2K, (long)HH * T2K, T2K, (long)HH * T2T, T2T, 0, 0, HH, 1, 0);

        // a[b,h] = s2 @ vT2^T fp32 : M=2048 N=256 Kd=2048
        gemm_mma<0, false><<<dim3(DD / 128, TT / 128, BB * HH), 256, SMEM_GEMM_BYTES>>>(
            s2, vT2, a, nullptr,
            TT, TT, 2 * TT, 2 * TT, DD, 0, 0,
            (long)HH * T2T, T2T, (long)DD * 2 * TT, 0, (long)HH * TD, TD, 0, 0, HH, 1, 0);

        ln_split_kernel<<<BB * HH * TT, 256>>>();

        // y2[b,t,h*K+n] = relu(a2 @ Dy2^T) * x (split, loOff=NN_)
        gemm_mma<3, false><<<dim3(KK / 128, TT / 128, BB * HH), 256, SMEM_GEMM_BYTES>>>(
            a2, Dy2, y2, x,
            DD, DD, 2 * DD, 2 * DD, 2 * NN_, KK, NN_,
            (long)HH * T2D, T2D, 0, (long)KK * 2 * DD,
            T2N, (long)KK, (long)HH * TK, TK, HH, 1, 0);

        // yE partials = y2 @ E2^T (split-K=2) : M=4096 N=256, Kd=2048/split
        gemm_mma<0, false><<<dim3(DD / 128, (BB * TT) / 128, 2), 256, SMEM_GEMM_BYTES>>>(
            y2, E2, yE, nullptr,
            NN_ / 2, NN_, 2 * NN_, 2 * NN_, DD, 0, 0,
            0, 0, 0, 0, 0, 0, 0, 0, 1, 2, 4096L * 256);

        combine_split_kernel<<<BB * TT, 256>>>();
    }

    // out = v2a @ ro2^T fp32 : M=4096 N=32000 Kd=256
    gemm_mma<0, false><<<dim3(BV / 128, (BB * TT) / 128, 1), 256, SMEM_GEMM_BYTES>>>(
        v2a, ro2, out, nullptr,
        DD, DD, 2 * DD, 2 * DD, BV, 0, 0,
        0, 0, 0, 0, 0, 0, 0, 0, 1, 1, 0);
}